// round 9
// baseline (speedup 1.0000x reference)
#include <cuda_runtime.h>

#define BB 32
#define NN 784
#define CC 256
#define FF 1024
#define MM (BB*NN)      // 25088
#define HEADS 8
#define DIMH 32

typedef unsigned long long u64;

// ---- f32x2 packed-math helpers ----
__device__ __forceinline__ u64 pk2(float lo, float hi) {
    u64 r; asm("mov.b64 %0,{%1,%2};" : "=l"(r) : "f"(lo), "f"(hi)); return r;
}
__device__ __forceinline__ void upk2(u64 v, float& lo, float& hi) {
    asm("mov.b64 {%0,%1},%2;" : "=f"(lo), "=f"(hi) : "l"(v));
}
__device__ __forceinline__ void fma2(u64& d, u64 a, u64 b) {
    asm("fma.rn.f32x2 %0,%1,%2,%3;" : "=l"(d) : "l"(a), "l"(b), "l"(d));
}

// ---------------- scratch ----------------
__device__ float g_x[(size_t)MM * FF];
__device__ float g_attn[(size_t)MM * 512];
__device__ float g_sum[FF];
__device__ float g_sumsq[FF];
__device__ float g_affa[FF];
__device__ float g_affb[FF];

__global__ void zero_stats_kernel() {
    int i = blockIdx.x * blockDim.x + threadIdx.x;
    if (i < FF) { g_sum[i] = 0.f; g_sumsq[i] = 0.f; }
}

// ---------------- SGEMM: C[M,N]=A[M,K]*B[K,N], 128x64 block, 8x4 micro ----------------
template<int KTOT, int LDA, int LDB, int LDC, bool STATS>
__global__ __launch_bounds__(256) void sgemm_kernel(
    const float* __restrict__ A, const float* __restrict__ Bm, float* __restrict__ C)
{
    __shared__ __align__(16) float As[16][128];
    __shared__ __align__(16) float Bs[16][64];
    __shared__ float csum[64], csq[64];

    const int m0 = blockIdx.y * 128;
    const int n0 = blockIdx.x * 64;
    const int tid = threadIdx.x;
    const int tx = tid & 15, ty = tid >> 4;

    float acc[8][4] = {};

    for (int k0 = 0; k0 < KTOT; k0 += 16) {
        #pragma unroll
        for (int r = 0; r < 2; r++) {
            int f4 = tid + r * 256;
            int m = f4 >> 2, kq = f4 & 3;
            float4 v = *reinterpret_cast<const float4*>(&A[(size_t)(m0 + m) * LDA + k0 + kq * 4]);
            As[kq*4+0][m] = v.x; As[kq*4+1][m] = v.y; As[kq*4+2][m] = v.z; As[kq*4+3][m] = v.w;
        }
        {
            int k = tid >> 4, nq = tid & 15;
            float4 v = *reinterpret_cast<const float4*>(&Bm[(size_t)(k0 + k) * LDB + n0 + nq * 4]);
            *reinterpret_cast<float4*>(&Bs[k][nq * 4]) = v;
        }
        __syncthreads();
        #pragma unroll
        for (int k = 0; k < 16; k++) {
            float4 a0 = *reinterpret_cast<const float4*>(&As[k][ty * 8]);
            float4 a1 = *reinterpret_cast<const float4*>(&As[k][ty * 8 + 4]);
            float4 b4 = *reinterpret_cast<const float4*>(&Bs[k][tx * 4]);
            float av[8] = {a0.x, a0.y, a0.z, a0.w, a1.x, a1.y, a1.z, a1.w};
            float bv[4] = {b4.x, b4.y, b4.z, b4.w};
            #pragma unroll
            for (int i = 0; i < 8; i++)
                #pragma unroll
                for (int j = 0; j < 4; j++)
                    acc[i][j] = fmaf(av[i], bv[j], acc[i][j]);
        }
        __syncthreads();
    }

    #pragma unroll
    for (int i = 0; i < 8; i++) {
        float4 o = make_float4(acc[i][0], acc[i][1], acc[i][2], acc[i][3]);
        *reinterpret_cast<float4*>(&C[(size_t)(m0 + ty * 8 + i) * LDC + n0 + tx * 4]) = o;
    }

    if (STATS) {
        if (tid < 64) { csum[tid] = 0.f; csq[tid] = 0.f; }
        __syncthreads();
        #pragma unroll
        for (int j = 0; j < 4; j++) {
            float s = 0.f, sq = 0.f;
            #pragma unroll
            for (int i = 0; i < 8; i++) { float v = acc[i][j]; s += v; sq = fmaf(v, v, sq); }
            atomicAdd(&csum[tx * 4 + j], s);
            atomicAdd(&csq[tx * 4 + j], sq);
        }
        __syncthreads();
        if (tid < 64) {
            atomicAdd(&g_sum[n0 + tid], csum[tid]);
            atomicAdd(&g_sumsq[n0 + tid], csq[tid]);
        }
    }
}

// ---------------- BN finalize ----------------
__global__ void bn_finalize_kernel(const float* __restrict__ bn_scale) {
    int f = blockIdx.x * blockDim.x + threadIdx.x;
    if (f < FF) {
        float mean = g_sum[f] * (1.f / MM);
        float var  = g_sumsq[f] * (1.f / MM) - mean * mean;
        float r = rsqrtf(var + 1e-5f);
        float a = r * bn_scale[f];
        g_affa[f] = a;
        g_affb[f] = -mean * a;
    }
}

// ---------------- fused flash attention: QT=112, KT=64, 224 threads, 8q x 4k/4vd ----------------
// Register-safe mix: S-phase SCALAR fp32 (two 4-row halves), PV f32x2 (proven spill-free).
// Fixed-shift softmax p = exp(s + bias - 20); l via tx==kk trick; layouts from round 5/7.
#define EXP_SHIFT 20.0f
#define AT_SMEM_FLOATS (112*32 + 64*32 + 64*64 + 112*68 + 256)
__global__ __launch_bounds__(224, 3) void attention_kernel(
    const float* __restrict__ bias, float* __restrict__ out)
{
    extern __shared__ __align__(16) float sm[];
    float* Qs = sm;                        // 3584
    float* Ks = sm + 3584;                 // 2048
    float* Vs = sm + 5632;                 // 4096
    float* Ss = sm + 9728;                 // 7616 (112*68)
    float* cA = sm + 17344;                // 128
    float* cB = sm + 17472;                // 128

    const int tid = threadIdx.x;
    const int tx = tid & 15, ty = tid >> 4;     // ty 0..13
    const int tx4 = tx * 4, ty8 = ty * 8;
    const int q0 = blockIdx.x * 112;
    const int h  = blockIdx.y;
    const int b  = blockIdx.z;

    if (tid < 128) {
        int seg = tid >> 5, d = tid & 31;
        int f = seg * 256 + h * 32 + d;
        cA[tid] = g_affa[f];
        cB[tid] = g_affb[f];
    }
    __syncthreads();

    // Q tile [112,32], normalized (784 = 7*112 -> no q masking)
    for (int idx = tid; idx < 112 * 32; idx += 224) {
        int q = idx >> 5, d = idx & 31;
        float v = g_x[(size_t)(b * NN + q0 + q) * FF + h * 32 + d];
        Qs[q * 32 + d] = fmaf(v, cA[d], cB[d]);
    }

    u64 acc2[8][2] = {};                     // out[8q][4vd] packed along vd
    float lacc[8] = {0.f,0.f,0.f,0.f,0.f,0.f,0.f,0.f};

    for (int kc = 0; kc < 13; kc++) {
        const int k0 = kc * 64;
        __syncthreads();   // protect Ks/Vs/Ss from previous-iteration consumers

        // K chunk [64,32], XOR-swizzled float4 groups
        for (int idx = tid; idx < 64 * 32; idx += 224) {
            int k = idx >> 5, d = idx & 31;
            int row = k0 + k;
            float v = (row < NN) ? fmaf(g_x[(size_t)(b * NN + row) * FF + 256 + h * 32 + d],
                                        cA[32 + d], cB[32 + d]) : 0.f;
            Ks[k * 32 + ((((d >> 2) ^ ((k >> 2) & 7)) << 2) | (d & 3))] = v;
        }
        // V chunk [64,64] (v1 | v2), plain
        for (int idx = tid; idx < 64 * 64; idx += 224) {
            int k = idx >> 6, d = idx & 63;
            int row = k0 + k;
            int col = 512 + ((d >> 5) << 8) + h * 32 + (d & 31);
            float v = (row < NN) ? fmaf(g_x[(size_t)(b * NN + row) * FF + col],
                                        cA[64 + d], cB[64 + d]) : 0.f;
            Vs[k * 64 + d] = v;
        }
        __syncthreads();

        // ---- S = Q K^T, SCALAR fp32, two 4-row halves; exp fused into the store ----
        const bool kvalid = (k0 + tx4 + 3) < NN;   // 784 % 4 == 0
        #pragma unroll
        for (int ih = 0; ih < 2; ih++) {
            const int qb = ty8 + ih * 4;
            float s[4][4] = {};
            #pragma unroll
            for (int dq = 0; dq < 8; dq++) {
                float4 kb[4];
                #pragma unroll
                for (int j = 0; j < 4; j++)
                    kb[j] = *reinterpret_cast<const float4*>(
                        &Ks[(tx4 + j) * 32 + ((dq ^ (tx & 7)) << 2)]);
                #pragma unroll
                for (int i = 0; i < 4; i++) {
                    float4 qa = *reinterpret_cast<const float4*>(
                        &Qs[(qb + i) * 32 + dq * 4]);
                    #pragma unroll
                    for (int j = 0; j < 4; j++) {
                        s[i][j] = fmaf(qa.x, kb[j].x, s[i][j]);
                        s[i][j] = fmaf(qa.y, kb[j].y, s[i][j]);
                        s[i][j] = fmaf(qa.z, kb[j].z, s[i][j]);
                        s[i][j] = fmaf(qa.w, kb[j].w, s[i][j]);
                    }
                }
            }
            if (kvalid) {
                #pragma unroll
                for (int i = 0; i < 4; i++) {
                    float4 bi = *reinterpret_cast<const float4*>(
                        &bias[(size_t)(q0 + qb + i) * NN + k0 + tx4]);
                    float p0 = __expf(s[i][0] + bi.x - EXP_SHIFT);
                    float p1 = __expf(s[i][1] + bi.y - EXP_SHIFT);
                    float p2 = __expf(s[i][2] + bi.z - EXP_SHIFT);
                    float p3 = __expf(s[i][3] + bi.w - EXP_SHIFT);
                    *reinterpret_cast<float4*>(&Ss[(qb + i) * 68 + tx4]) =
                        make_float4(p0, p1, p2, p3);
                }
            } else {
                #pragma unroll
                for (int i = 0; i < 4; i++)
                    *reinterpret_cast<float4*>(&Ss[(qb + i) * 68 + tx4]) =
                        make_float4(0.f, 0.f, 0.f, 0.f);
            }
        }
        __syncthreads();

        // ---- PV accumulate (f32x2 along vd) + free l accumulation ----
        #pragma unroll
        for (int kk = 0; kk < 16; kk++) {
            float4 P[8];
            #pragma unroll
            for (int i = 0; i < 8; i++)
                P[i] = *reinterpret_cast<const float4*>(&Ss[(ty8 + i) * 68 + kk * 4]);
            if (tx == kk) {
                #pragma unroll
                for (int i = 0; i < 8; i++)
                    lacc[i] += (P[i].x + P[i].y) + (P[i].z + P[i].w);
            }
            #pragma unroll
            for (int c = 0; c < 4; c++) {
                ulonglong2 vv = *reinterpret_cast<const ulonglong2*>(
                    &Vs[(kk * 4 + c) * 64 + tx4]);
                #pragma unroll
                for (int i = 0; i < 8; i++) {
                    float p = (c == 0) ? P[i].x : (c == 1) ? P[i].y : (c == 2) ? P[i].z : P[i].w;
                    u64 pp = pk2(p, p);
                    fma2(acc2[i][0], pp, vv.x);
                    fma2(acc2[i][1], pp, vv.y);
                }
            }
        }
    }

    // ---- reduce l across the 16-lane tx group ----
    #pragma unroll
    for (int i = 0; i < 8; i++) {
        #pragma unroll
        for (int d = 1; d < 16; d <<= 1)
            lacc[i] += __shfl_xor_sync(0xffffffffu, lacc[i], d);
    }

    // ---- epilogue: /l, hard_swish, write [ (b*N+q), h*64 + vd ] ----
    #pragma unroll
    for (int i = 0; i < 8; i++) {
        int q = ty8 + i;
        float inv = 1.0f / lacc[i];
        float v0, v1, v2, v3;
        upk2(acc2[i][0], v0, v1);
        upk2(acc2[i][1], v2, v3);
        v0 *= inv; v1 *= inv; v2 *= inv; v3 *= inv;
        float o0 = v0 * __saturatef((v0 + 3.0f) * (1.0f / 6.0f));
        float o1 = v1 * __saturatef((v1 + 3.0f) * (1.0f / 6.0f));
        float o2 = v2 * __saturatef((v2 + 3.0f) * (1.0f / 6.0f));
        float o3 = v3 * __saturatef((v3 + 3.0f) * (1.0f / 6.0f));
        *reinterpret_cast<float4*>(&out[((size_t)(b * NN + q0 + q)) * 512 + h * 64 + tx4]) =
            make_float4(o0, o1, o2, o3);
    }
}

// ---------------- launch ----------------
extern "C" void kernel_launch(void* const* d_in, const int* in_sizes, int n_in,
                              void* d_out, int out_size) {
    const float* inputs    = (const float*)d_in[0];
    const float* w_qkv     = (const float*)d_in[1];
    const float* bn_scale  = (const float*)d_in[2];
    const float* attn_bias = (const float*)d_in[3];
    const float* w_out     = (const float*)d_in[4];
    float* out = (float*)d_out;

    float *px, *pattn;
    cudaGetSymbolAddress((void**)&px, g_x);
    cudaGetSymbolAddress((void**)&pattn, g_attn);

    const int at_smem = AT_SMEM_FLOATS * 4;   // 70400 bytes
    cudaFuncSetAttribute(attention_kernel,
                         cudaFuncAttributeMaxDynamicSharedMemorySize, at_smem);

    zero_stats_kernel<<<4, 256>>>();
    sgemm_kernel<256, 256, 1024, 1024, true><<<dim3(16, 196), 256>>>(inputs, w_qkv, px);
    bn_finalize_kernel<<<4, 256>>>(bn_scale);
    attention_kernel<<<dim3(7, HEADS, BB), 224, at_smem>>>(attn_bias, pattn);
    sgemm_kernel<512, 512, 256, 256, false><<<dim3(4, 196), 256>>>(pattn, w_out, out);
}

// round 11
// speedup vs baseline: 3.4873x; 3.4873x over previous
#include <cuda_runtime.h>

#define BB 32
#define NN 784
#define CC 256
#define FF 1024
#define MM (BB*NN)      // 25088
#define HEADS 8
#define DIMH 32

typedef unsigned long long u64;

// ---- f32x2 packed-math helpers ----
__device__ __forceinline__ u64 pk2(float lo, float hi) {
    u64 r; asm("mov.b64 %0,{%1,%2};" : "=l"(r) : "f"(lo), "f"(hi)); return r;
}
__device__ __forceinline__ void upk2(u64 v, float& lo, float& hi) {
    asm("mov.b64 {%0,%1},%2;" : "=f"(lo), "=f"(hi) : "l"(v));
}
__device__ __forceinline__ void fma2(u64& d, u64 a, u64 b) {
    asm("fma.rn.f32x2 %0,%1,%2,%3;" : "=l"(d) : "l"(a), "l"(b), "l"(d));
}

// ---------------- scratch ----------------
__device__ float g_x[(size_t)MM * FF];
__device__ float g_attn[(size_t)MM * 512];
__device__ float g_sum[FF];
__device__ float g_sumsq[FF];
__device__ float g_affa[FF];
__device__ float g_affb[FF];

__global__ void zero_stats_kernel() {
    int i = blockIdx.x * blockDim.x + threadIdx.x;
    if (i < FF) { g_sum[i] = 0.f; g_sumsq[i] = 0.f; }
}

// ---------------- SGEMM: C[M,N]=A[M,K]*B[K,N], 128x128 block, 8x8 micro (split +-64) ----------------
// Thread (tx 0..15, ty 0..15): rows {ty*4+i, 64+ty*4+i}, cols {tx*4+j, 64+tx*4+j}.
// All inner-loop LDS are 16B-stride across lanes -> conflict-free.
template<int KTOT, int LDA, int LDB, int LDC, bool STATS>
__global__ __launch_bounds__(256, 2) void sgemm_kernel(
    const float* __restrict__ A, const float* __restrict__ Bm, float* __restrict__ C)
{
    __shared__ __align__(16) float As[16][128];
    __shared__ __align__(16) float Bs[16][128];
    __shared__ float csum[128], csq[128];

    const int m0 = blockIdx.y * 128;
    const int n0 = blockIdx.x * 128;
    const int tid = threadIdx.x;
    const int tx = tid & 15, ty = tid >> 4;
    const int tx4 = tx * 4, ty4 = ty * 4;

    float acc[8][8] = {};

    for (int k0 = 0; k0 < KTOT; k0 += 16) {
        // A tile 128x16 -> As[16][128] (transposed scatter), 2 float4/thread
        #pragma unroll
        for (int r = 0; r < 2; r++) {
            int f4 = tid + r * 256;
            int m = f4 >> 2, kq = f4 & 3;
            float4 v = *reinterpret_cast<const float4*>(&A[(size_t)(m0 + m) * LDA + k0 + kq * 4]);
            As[kq*4+0][m] = v.x; As[kq*4+1][m] = v.y; As[kq*4+2][m] = v.z; As[kq*4+3][m] = v.w;
        }
        // B tile 16x128 -> Bs[16][128], 2 float4/thread
        #pragma unroll
        for (int r = 0; r < 2; r++) {
            int f4 = tid + r * 256;
            int k = f4 >> 5, n4 = f4 & 31;
            float4 v = *reinterpret_cast<const float4*>(&Bm[(size_t)(k0 + k) * LDB + n0 + n4 * 4]);
            *reinterpret_cast<float4*>(&Bs[k][n4 * 4]) = v;
        }
        __syncthreads();
        #pragma unroll
        for (int k = 0; k < 16; k++) {
            float4 a0 = *reinterpret_cast<const float4*>(&As[k][ty4]);
            float4 a1 = *reinterpret_cast<const float4*>(&As[k][64 + ty4]);
            float4 b0 = *reinterpret_cast<const float4*>(&Bs[k][tx4]);
            float4 b1 = *reinterpret_cast<const float4*>(&Bs[k][64 + tx4]);
            float av[8] = {a0.x, a0.y, a0.z, a0.w, a1.x, a1.y, a1.z, a1.w};
            float bv[8] = {b0.x, b0.y, b0.z, b0.w, b1.x, b1.y, b1.z, b1.w};
            #pragma unroll
            for (int i = 0; i < 8; i++)
                #pragma unroll
                for (int j = 0; j < 8; j++)
                    acc[i][j] = fmaf(av[i], bv[j], acc[i][j]);
        }
        __syncthreads();
    }

    // store: rows {ty4+i, 64+ty4+i}, col blocks {tx4, 64+tx4}
    #pragma unroll
    for (int i = 0; i < 8; i++) {
        int row = m0 + ((i < 4) ? (ty4 + i) : (64 + ty4 + i - 4));
        *reinterpret_cast<float4*>(&C[(size_t)row * LDC + n0 + tx4]) =
            make_float4(acc[i][0], acc[i][1], acc[i][2], acc[i][3]);
        *reinterpret_cast<float4*>(&C[(size_t)row * LDC + n0 + 64 + tx4]) =
            make_float4(acc[i][4], acc[i][5], acc[i][6], acc[i][7]);
    }

    if (STATS) {
        if (tid < 128) { csum[tid] = 0.f; csq[tid] = 0.f; }
        __syncthreads();
        #pragma unroll
        for (int j = 0; j < 8; j++) {
            int col = (j < 4) ? (tx4 + j) : (64 + tx4 + j - 4);
            float s = 0.f, sq = 0.f;
            #pragma unroll
            for (int i = 0; i < 8; i++) { float v = acc[i][j]; s += v; sq = fmaf(v, v, sq); }
            atomicAdd(&csum[col], s);
            atomicAdd(&csq[col], sq);
        }
        __syncthreads();
        if (tid < 128) {
            atomicAdd(&g_sum[n0 + tid], csum[tid]);
            atomicAdd(&g_sumsq[n0 + tid], csq[tid]);
        }
    }
}

// ---------------- BN finalize ----------------
__global__ void bn_finalize_kernel(const float* __restrict__ bn_scale) {
    int f = blockIdx.x * blockDim.x + threadIdx.x;
    if (f < FF) {
        float mean = g_sum[f] * (1.f / MM);
        float var  = g_sumsq[f] * (1.f / MM) - mean * mean;
        float r = rsqrtf(var + 1e-5f);
        float a = r * bn_scale[f];
        g_affa[f] = a;
        g_affb[f] = -mean * a;
    }
}

// ---------------- fused flash attention (round-7 verbatim): QT=56, KT=64, 224 thr, 4x4 ----------------
// Fixed-shift softmax: p = exp(s + bias - 20). No max pass, no rescale, no m/l state.
// l accumulated inside PV by thread tx==kk, shfl-reduced once at end.
#define EXP_SHIFT 20.0f
__global__ __launch_bounds__(224, 4) void attention_kernel(
    const float* __restrict__ bias, float* __restrict__ out)
{
    __shared__ __align__(16) float Qs[56 * 32];
    __shared__ __align__(16) float Ks[64 * 32];
    __shared__ __align__(16) float Vs[64 * 64];
    __shared__ __align__(16) float Ss[56 * 68];
    __shared__ float cA[128], cB[128];

    const int tid = threadIdx.x;
    const int tx = tid & 15, ty = tid >> 4;       // ty 0..13
    const int tx4 = tx * 4, ty4 = ty * 4;
    const int q0 = blockIdx.x * 56;
    const int h  = blockIdx.y;
    const int b  = blockIdx.z;

    if (tid < 128) {
        int seg = tid >> 5, d = tid & 31;
        int f = seg * 256 + h * 32 + d;
        cA[tid] = g_affa[f];
        cB[tid] = g_affb[f];
    }
    __syncthreads();

    // Q tile [56,32], normalized
    for (int idx = tid; idx < 56 * 32; idx += 224) {
        int q = idx >> 5, d = idx & 31;
        float v = g_x[(size_t)(b * NN + q0 + q) * FF + h * 32 + d];
        Qs[q * 32 + d] = fmaf(v, cA[d], cB[d]);
    }

    u64 acc2[4][2] = {};            // out[q 4][vd pairs 2], packed along vd
    float lacc[4] = {0.f, 0.f, 0.f, 0.f};

    for (int kc = 0; kc < 13; kc++) {
        const int k0 = kc * 64;
        __syncthreads();  // protect Ks/Vs/Ss from previous-iteration consumers

        // K chunk [64,32], XOR-swizzled on the float4 group
        for (int idx = tid; idx < 64 * 32; idx += 224) {
            int k = idx >> 5, d = idx & 31;
            int row = k0 + k;
            float v = (row < NN) ? fmaf(g_x[(size_t)(b * NN + row) * FF + 256 + h * 32 + d],
                                        cA[32 + d], cB[32 + d]) : 0.f;
            Ks[k * 32 + ((((d >> 2) ^ ((k >> 2) & 7)) << 2) | (d & 3))] = v;
        }
        // V chunk [64,64] (v1 | v2), plain
        for (int idx = tid; idx < 64 * 64; idx += 224) {
            int k = idx >> 6, d = idx & 63;
            int row = k0 + k;
            int col = 512 + ((d >> 5) << 8) + h * 32 + (d & 31);
            float v = (row < NN) ? fmaf(g_x[(size_t)(b * NN + row) * FF + col],
                                        cA[64 + d], cB[64 + d]) : 0.f;
            Vs[k * 64 + d] = v;
        }
        __syncthreads();

        // ---- S = Q K^T (f32x2 packed along d), then P = exp(S + bias - 20) ----
        {
            u64 s2[4][4] = {};
            #pragma unroll
            for (int dq = 0; dq < 8; dq++) {
                ulonglong2 kb[4];
                #pragma unroll
                for (int j = 0; j < 4; j++)
                    kb[j] = *reinterpret_cast<const ulonglong2*>(
                        &Ks[(tx4 + j) * 32 + ((dq ^ (tx & 7)) << 2)]);
                #pragma unroll
                for (int i = 0; i < 4; i++) {
                    ulonglong2 qa = *reinterpret_cast<const ulonglong2*>(
                        &Qs[(ty4 + i) * 32 + dq * 4]);
                    #pragma unroll
                    for (int j = 0; j < 4; j++) {
                        fma2(s2[i][j], qa.x, kb[j].x);
                        fma2(s2[i][j], qa.y, kb[j].y);
                    }
                }
            }
            if (k0 + tx4 + 3 < NN) {   // 784 % 4 == 0 -> whole float4 valid or invalid
                #pragma unroll
                for (int i = 0; i < 4; i++) {
                    float4 bi = *reinterpret_cast<const float4*>(
                        &bias[(size_t)(q0 + ty4 + i) * NN + k0 + tx4]);
                    float lo, hi;
                    float p0, p1, p2, p3;
                    upk2(s2[i][0], lo, hi); p0 = __expf(lo + hi + bi.x - EXP_SHIFT);
                    upk2(s2[i][1], lo, hi); p1 = __expf(lo + hi + bi.y - EXP_SHIFT);
                    upk2(s2[i][2], lo, hi); p2 = __expf(lo + hi + bi.z - EXP_SHIFT);
                    upk2(s2[i][3], lo, hi); p3 = __expf(lo + hi + bi.w - EXP_SHIFT);
                    *reinterpret_cast<float4*>(&Ss[(ty4 + i) * 68 + tx4]) =
                        make_float4(p0, p1, p2, p3);
                }
            } else {
                #pragma unroll
                for (int i = 0; i < 4; i++)
                    *reinterpret_cast<float4*>(&Ss[(ty4 + i) * 68 + tx4]) =
                        make_float4(0.f, 0.f, 0.f, 0.f);
            }
        }
        __syncthreads();

        // ---- PV accumulate (f32x2 packed along vd) + free l accumulation ----
        #pragma unroll
        for (int kk = 0; kk < 16; kk++) {
            float4 P[4];
            #pragma unroll
            for (int i = 0; i < 4; i++)
                P[i] = *reinterpret_cast<const float4*>(&Ss[(ty4 + i) * 68 + kk * 4]);
            if (tx == kk) {   // each kk-slice counted exactly once across the tx group
                #pragma unroll
                for (int i = 0; i < 4; i++)
                    lacc[i] += (P[i].x + P[i].y) + (P[i].z + P[i].w);
            }
            #pragma unroll
            for (int c = 0; c < 4; c++) {
                ulonglong2 vv = *reinterpret_cast<const ulonglong2*>(
                    &Vs[(kk * 4 + c) * 64 + tx4]);
                #pragma unroll
                for (int i = 0; i < 4; i++) {
                    float p = (c == 0) ? P[i].x : (c == 1) ? P[i].y : (c == 2) ? P[i].z : P[i].w;
                    u64 pp = pk2(p, p);
                    fma2(acc2[i][0], pp, vv.x);
                    fma2(acc2[i][1], pp, vv.y);
                }
            }
        }
    }

    // ---- reduce l across the 16-lane tx group ----
    #pragma unroll
    for (int i = 0; i < 4; i++) {
        #pragma unroll
        for (int d = 1; d < 16; d <<= 1)
            lacc[i] += __shfl_xor_sync(0xffffffffu, lacc[i], d);
    }

    // ---- epilogue: /l, hard_swish, write [ (b*N+q), h*64 + vd ] ----
    #pragma unroll
    for (int i = 0; i < 4; i++) {
        int q = ty4 + i;
        float inv = 1.0f / lacc[i];
        float v0, v1, v2, v3;
        upk2(acc2[i][0], v0, v1);
        upk2(acc2[i][1], v2, v3);
        v0 *= inv; v1 *= inv; v2 *= inv; v3 *= inv;
        float o[4];
        o[0] = v0 * __saturatef((v0 + 3.0f) * (1.0f / 6.0f));
        o[1] = v1 * __saturatef((v1 + 3.0f) * (1.0f / 6.0f));
        o[2] = v2 * __saturatef((v2 + 3.0f) * (1.0f / 6.0f));
        o[3] = v3 * __saturatef((v3 + 3.0f) * (1.0f / 6.0f));
        *reinterpret_cast<float4*>(&out[((size_t)(b * NN + q0 + q)) * 512 + h * 64 + tx4]) =
            make_float4(o[0], o[1], o[2], o[3]);
    }
}

// ---------------- launch ----------------
extern "C" void kernel_launch(void* const* d_in, const int* in_sizes, int n_in,
                              void* d_out, int out_size) {
    const float* inputs    = (const float*)d_in[0];
    const float* w_qkv     = (const float*)d_in[1];
    const float* bn_scale  = (const float*)d_in[2];
    const float* attn_bias = (const float*)d_in[3];
    const float* w_out     = (const float*)d_in[4];
    float* out = (float*)d_out;

    float *px, *pattn;
    cudaGetSymbolAddress((void**)&px, g_x);
    cudaGetSymbolAddress((void**)&pattn, g_attn);

    zero_stats_kernel<<<4, 256>>>();
    // x = inputs @ w_qkv, fused per-feature sum/sumsq  (N=1024 -> 8 col-blocks)
    sgemm_kernel<256, 256, 1024, 1024, true><<<dim3(8, 196), 256>>>(inputs, w_qkv, px);
    bn_finalize_kernel<<<4, 256>>>(bn_scale);
    attention_kernel<<<dim3(14, HEADS, BB), 224>>>(attn_bias, pattn);
    // final projection (N=256 -> 2 col-blocks)
    sgemm_kernel<512, 512, 256, 256, false><<<dim3(2, 196), 256>>>(pattn, w_out, out);
}